// round 4
// baseline (speedup 1.0000x reference)
#include <cuda_runtime.h>
#include <cuda_bf16.h>
#include <mma.h>
#include <math.h>

using namespace nvcuda;

// ---------------- problem constants ----------------
#define BB 2
#define LL 2048
#define NC 3
#define DMC 256
#define DM 768          // DMC*NC
#define DI 1536         // 2*DM
#define DS 16
#define DR 48
#define DCV 4
#define NLAY 4
#define DXP 80          // DR + 2*DS
#define NROWS (BB*LL)   // 4096

// ---------------- scratch (device globals; no allocs) ----------------
__device__ float g_H[NROWS*DM];
__device__ float g_XZ[NROWS*2*DI];
__device__ float g_U[NROWS*DI];
__device__ float g_DBC[NROWS*DXP];
__device__ float g_DELTA[NROWS*DI];

// bf16 hi/lo operand buffers
__device__ __nv_bfloat16 g_XNh[NROWS*DM],  g_XNl[NROWS*DM];
__device__ __nv_bfloat16 g_Uh[NROWS*DI],   g_Ul[NROWS*DI];
__device__ __nv_bfloat16 g_DBCh[NROWS*DXP],g_DBCl[NROWS*DXP];
__device__ __nv_bfloat16 g_Yh[NROWS*DI],   g_Yl[NROWS*DI];

// bf16 hi/lo weights (all layers)
__device__ __nv_bfloat16 g_Wih[NLAY*2*DI*DM], g_Wil[NLAY*2*DI*DM];
__device__ __nv_bfloat16 g_Wxh[NLAY*DXP*DI],  g_Wxl[NLAY*DXP*DI];
__device__ __nv_bfloat16 g_Wdh[NLAY*DI*DR],   g_Wdl[NLAY*DI*DR];
__device__ __nv_bfloat16 g_Woh[NLAY*DM*DI],   g_Wol[NLAY*DM*DI];

__device__ __forceinline__ void split_bf16(float x, __nv_bfloat16& h, __nv_bfloat16& l) {
    h = __float2bfloat16(x);
    l = __float2bfloat16(x - __bfloat162float(h));
}

// ---------------- fp32 -> bf16 hi/lo split ----------------
__global__ void split_kernel(const float* __restrict__ w,
                             __nv_bfloat16* __restrict__ hi,
                             __nv_bfloat16* __restrict__ lo, int n) {
    int i = blockIdx.x * blockDim.x + threadIdx.x;
    if (i >= n) return;
    __nv_bfloat16 h, l;
    split_bf16(w[i], h, l);
    hi[i] = h; lo[i] = l;
}

// ---------------- embedding gather ----------------
__global__ void embed_kernel(const int* __restrict__ tokens,
                             const float* __restrict__ emb) {
    int i = blockIdx.x * blockDim.x + threadIdx.x;
    if (i >= NROWS*DM) return;
    int row = i / DM;
    int col = i % DM;
    int c = col / DMC, j = col % DMC;
    int tok = tokens[row*NC + c];
    g_H[i] = emb[tok*DMC + j];
}

// ---------------- rmsnorm -> fp32 out ----------------
__global__ void rmsnorm_kernel(const float* __restrict__ in,
                               const float* __restrict__ w,
                               float* __restrict__ out) {
    int row = blockIdx.x;
    const float* x = in + (size_t)row*DM;
    float s = 0.f;
    for (int i = threadIdx.x; i < DM; i += 256) { float v = x[i]; s += v*v; }
    __shared__ float red[256];
    red[threadIdx.x] = s;
    __syncthreads();
    for (int o = 128; o; o >>= 1) {
        if (threadIdx.x < o) red[threadIdx.x] += red[threadIdx.x + o];
        __syncthreads();
    }
    float scale = rsqrtf(red[0] / (float)DM + 1e-5f);
    for (int i = threadIdx.x; i < DM; i += 256)
        out[(size_t)row*DM + i] = x[i] * scale * w[i];
}

// ---------------- rmsnorm -> bf16 hi/lo out ----------------
__global__ void rmsnorm_split_kernel(const float* __restrict__ in,
                                     const float* __restrict__ w,
                                     __nv_bfloat16* __restrict__ oh,
                                     __nv_bfloat16* __restrict__ ol) {
    int row = blockIdx.x;
    const float* x = in + (size_t)row*DM;
    float s = 0.f;
    for (int i = threadIdx.x; i < DM; i += 256) { float v = x[i]; s += v*v; }
    __shared__ float red[256];
    red[threadIdx.x] = s;
    __syncthreads();
    for (int o = 128; o; o >>= 1) {
        if (threadIdx.x < o) red[threadIdx.x] += red[threadIdx.x + o];
        __syncthreads();
    }
    float scale = rsqrtf(red[0] / (float)DM + 1e-5f);
    for (int i = threadIdx.x; i < DM; i += 256) {
        float v = x[i] * scale * w[i];
        __nv_bfloat16 h, l;
        split_bf16(v, h, l);
        oh[(size_t)row*DM + i] = h;
        ol[(size_t)row*DM + i] = l;
    }
}

// ---------------- zero fill ----------------
__global__ void zero_kernel(float* __restrict__ p, int n) {
    int i = blockIdx.x * blockDim.x + threadIdx.x;
    if (i < n) p[i] = 0.f;
}

// ============================================================
// Tensor-core GEMM with bf16 hi/lo emulation (3 MMAs per product).
// C[M,N] = A[M,K] * W[N,K]^T, A/W given as bf16 hi+lo pairs.
// Block tile 128x128, K-tile 32, 8 warps (4m x 2n), warp tile 32x64.
// EPI: 0 = store fp32, 2 = softplus(acc+bias[n]), 3 = atomicAdd
// ============================================================
#define TM 128
#define TN 128
#define TK 32
#define TLD 40   // padded smem leading dim (elements)

template<int EPI>
__global__ __launch_bounds__(256)
void mmgemm(const __nv_bfloat16* __restrict__ Ah, const __nv_bfloat16* __restrict__ Al,
            const __nv_bfloat16* __restrict__ Wh, const __nv_bfloat16* __restrict__ Wl,
            float* __restrict__ C, const float* __restrict__ bias,
            int N, int Kmax, int lda, int ldw, int kchunk) {
    __shared__ __nv_bfloat16 sAh[TM*TLD], sAl[TM*TLD];
    __shared__ __nv_bfloat16 sBh[TN*TLD], sBl[TN*TLD];

    int m0 = blockIdx.y * TM;
    int n0 = blockIdx.x * TN;
    int kb = blockIdx.z * kchunk;
    int ke = kb + kchunk;

    int tid  = threadIdx.x;
    int row  = tid >> 1;          // 0..127
    int koff = (tid & 1) * 16;    // 0 or 16
    int warp = tid >> 5;
    int lid  = tid & 31;
    int wm = warp & 3;            // 0..3 -> m offset wm*32
    int wn = warp >> 2;           // 0..1 -> n offset wn*64

    wmma::fragment<wmma::accumulator, 16, 16, 16, float> acc[2][4];
    #pragma unroll
    for (int i = 0; i < 2; i++)
        #pragma unroll
        for (int j = 0; j < 4; j++)
            wmma::fill_fragment(acc[i][j], 0.f);

    bool wrow_ok = (n0 + row) < N;
    const __nv_bfloat16* apH = Ah + (size_t)(m0 + row) * lda;
    const __nv_bfloat16* apL = Al + (size_t)(m0 + row) * lda;
    const __nv_bfloat16* wpH = Wh + (size_t)(wrow_ok ? (n0 + row) : 0) * ldw;
    const __nv_bfloat16* wpL = Wl + (size_t)(wrow_ok ? (n0 + row) : 0) * ldw;

    for (int kt = kb; kt < ke; kt += TK) {
        #pragma unroll
        for (int h = 0; h < 2; h++) {
            int kc = kt + koff + h*8;
            uint4 z = make_uint4(0,0,0,0);
            bool kok = kc < Kmax;
            uint4 vah = kok ? *(const uint4*)(apH + kc) : z;
            uint4 val = kok ? *(const uint4*)(apL + kc) : z;
            uint4 vwh = (kok && wrow_ok) ? *(const uint4*)(wpH + kc) : z;
            uint4 vwl = (kok && wrow_ok) ? *(const uint4*)(wpL + kc) : z;
            int so = row*TLD + koff + h*8;
            *(uint4*)(sAh + so) = vah;
            *(uint4*)(sAl + so) = val;
            *(uint4*)(sBh + so) = vwh;
            *(uint4*)(sBl + so) = vwl;
        }
        __syncthreads();

        #pragma unroll
        for (int ks = 0; ks < TK; ks += 16) {
            wmma::fragment<wmma::matrix_a, 16, 16, 16, __nv_bfloat16, wmma::row_major> fah[2], fal[2];
            wmma::fragment<wmma::matrix_b, 16, 16, 16, __nv_bfloat16, wmma::col_major> fbh[4], fbl[4];
            #pragma unroll
            for (int i = 0; i < 2; i++) {
                wmma::load_matrix_sync(fah[i], sAh + (wm*32 + 16*i)*TLD + ks, TLD);
                wmma::load_matrix_sync(fal[i], sAl + (wm*32 + 16*i)*TLD + ks, TLD);
            }
            #pragma unroll
            for (int j = 0; j < 4; j++) {
                wmma::load_matrix_sync(fbh[j], sBh + (wn*64 + 16*j)*TLD + ks, TLD);
                wmma::load_matrix_sync(fbl[j], sBl + (wn*64 + 16*j)*TLD + ks, TLD);
            }
            #pragma unroll
            for (int i = 0; i < 2; i++)
                #pragma unroll
                for (int j = 0; j < 4; j++) {
                    wmma::mma_sync(acc[i][j], fah[i], fbh[j], acc[i][j]);
                    wmma::mma_sync(acc[i][j], fah[i], fbl[j], acc[i][j]);
                    wmma::mma_sync(acc[i][j], fal[i], fbh[j], acc[i][j]);
                }
        }
        __syncthreads();
    }

    if (EPI == 0) {
        #pragma unroll
        for (int i = 0; i < 2; i++)
            #pragma unroll
            for (int j = 0; j < 4; j++) {
                wmma::store_matrix_sync(C + (size_t)(m0 + wm*32 + 16*i)*N + n0 + wn*64 + 16*j,
                                        acc[i][j], N, wmma::mem_row_major);
            }
    } else {
        // per-warp staging in reused sAh region (8 warps x 320 floats = 2560 floats = sAh bytes)
        float* scratch = reinterpret_cast<float*>(sAh) + warp * 320;
        #pragma unroll
        for (int i = 0; i < 2; i++)
            #pragma unroll
            for (int j = 0; j < 4; j++) {
                __syncwarp();
                wmma::store_matrix_sync(scratch, acc[i][j], 20, wmma::mem_row_major);
                __syncwarp();
                #pragma unroll
                for (int e = 0; e < 8; e++) {
                    int idx = lid*8 + e;
                    int r = idx >> 4, c = idx & 15;
                    int n = n0 + wn*64 + 16*j + c;
                    if (n < N) {
                        int m = m0 + wm*32 + 16*i + r;
                        size_t o = (size_t)m*N + n;
                        float v = scratch[r*20 + c];
                        if (EPI == 2) {
                            float t = v + bias[n];
                            C[o] = (t > 20.f) ? t : log1pf(expf(t));
                        } else {
                            atomicAdd(&C[o], v);
                        }
                    }
                }
            }
    }
}

// ---------------- depthwise causal conv + bias + silu -> U fp32 + hi/lo ----------------
__global__ void conv_silu_kernel(const float* __restrict__ cw,
                                 const float* __restrict__ cb) {
    int i = blockIdx.x * blockDim.x + threadIdx.x;
    if (i >= NROWS*DI) return;
    int d = i % DI;
    int row = i / DI;
    int t = row % LL, b = row / LL;
    float w0 = cw[d*DCV + 0], w1 = cw[d*DCV + 1], w2 = cw[d*DCV + 2], w3 = cw[d*DCV + 3];
    float acc = cb[d];
    const float* base = g_XZ + (size_t)(b*LL)*(2*DI) + d;
    if (t >= 3) acc += base[(size_t)(t-3)*(2*DI)] * w0;
    if (t >= 2) acc += base[(size_t)(t-2)*(2*DI)] * w1;
    if (t >= 1) acc += base[(size_t)(t-1)*(2*DI)] * w2;
    acc += base[(size_t)t*(2*DI)] * w3;
    float y = acc / (1.f + expf(-acc));
    g_U[i] = y;
    __nv_bfloat16 h, l;
    split_bf16(y, h, l);
    g_Uh[i] = h; g_Ul[i] = l;
}

// ---------------- selective scan + skip + gating -> Y hi/lo ----------------
__global__ void scan_kernel(const float* __restrict__ A_log_l,
                            const float* __restrict__ D_l) {
    int g = threadIdx.x >> 4;
    int s = threadIdx.x & 15;
    int ch = blockIdx.x * 16 + g;
    int b = ch / DI, d = ch % DI;

    float A = -expf(A_log_l[d*DS + s]);
    float Dd = D_l[d];
    float h = 0.f;

    const float* delta_p = g_DELTA + (size_t)(b*LL)*DI + d;
    const float* u_p     = g_U     + (size_t)(b*LL)*DI + d;
    const float* z_p     = g_XZ    + (size_t)(b*LL)*(2*DI) + DI + d;
    const float* dbc_p   = g_DBC   + (size_t)(b*LL)*DXP;
    size_t ybase         = (size_t)(b*LL)*DI + d;

    for (int t = 0; t < LL; t++) {
        float dt = delta_p[(size_t)t*DI];
        float ut = u_p[(size_t)t*DI];
        float Bs = dbc_p[(size_t)t*DXP + DR + s];
        float Cs = dbc_p[(size_t)t*DXP + DR + DS + s];
        float dA = __expf(dt * A);
        h = dA * h + (dt * ut) * Bs;
        float yv = h * Cs;
        yv += __shfl_down_sync(0xffffffffu, yv, 8, 16);
        yv += __shfl_down_sync(0xffffffffu, yv, 4, 16);
        yv += __shfl_down_sync(0xffffffffu, yv, 2, 16);
        yv += __shfl_down_sync(0xffffffffu, yv, 1, 16);
        if (s == 0) {
            float z = z_p[(size_t)t*(2*DI)];
            float silu_z = z / (1.f + __expf(-z));
            float yo = (yv + ut * Dd) * silu_z;
            __nv_bfloat16 hh, ll;
            split_bf16(yo, hh, ll);
            g_Yh[ybase + (size_t)t*DI] = hh;
            g_Yl[ybase + (size_t)t*DI] = ll;
        }
    }
}

// ---------------- heads ----------------
__global__ void topic_kernel(const float* __restrict__ xfin,
                             const float* __restrict__ tw,
                             const float* __restrict__ tb,
                             float* __restrict__ out) {
    int w = threadIdx.x >> 5, lane = threadIdx.x & 31;
    if (w >= BB*3) return;
    int b = w / 3, c = w % 3;
    const float* p  = xfin + (size_t)(b*LL)*DM;
    const float* wt = tw + (size_t)c*DM;
    float s = 0.f;
    for (int i = lane; i < DM; i += 32) s += p[i] * wt[i];
    for (int o = 16; o; o >>= 1) s += __shfl_down_sync(0xffffffffu, s, o);
    if (lane == 0) out[b*3 + c] = s + tb[c];
}

__global__ void loss_kernel(float* __restrict__ out, const int* __restrict__ labels) {
    if (threadIdx.x != 0 || blockIdx.x != 0) return;
    float sum = 0.f, cnt = 0.f;
    for (int b = 0; b < BB; b++) {
        float t0 = out[b*3+0], t1 = out[b*3+1], t2 = out[b*3+2];
        float m = fmaxf(t0, fmaxf(t1, t2));
        float lse = m + logf(expf(t0-m) + expf(t1-m) + expf(t2-m));
        int lab = labels[b];
        float nll = lse - out[b*3 + lab];
        if (lab != 0) { sum += nll; cnt += 1.f; }
    }
    out[6] = sum / fmaxf(cnt, 1.f);
}

// ---------------- driver ----------------
extern "C" void kernel_launch(void* const* d_in, const int* in_sizes, int n_in,
                              void* d_out, int out_size) {
    const int*   tokens    = (const int*)  d_in[0];
    const int*   labels    = (const int*)  d_in[1];
    const float* emb       = (const float*)d_in[2];
    const float* in_proj_w = (const float*)d_in[3];
    const float* conv_w    = (const float*)d_in[4];
    const float* conv_b    = (const float*)d_in[5];
    const float* x_proj_w  = (const float*)d_in[6];
    const float* dt_proj_w = (const float*)d_in[7];
    const float* dt_proj_b = (const float*)d_in[8];
    const float* A_log     = (const float*)d_in[9];
    const float* Dp        = (const float*)d_in[10];
    const float* out_proj_w= (const float*)d_in[11];
    const float* norm_w    = (const float*)d_in[12];
    const float* norm_f_w  = (const float*)d_in[13];
    const float* topic_w   = (const float*)d_in[14];
    const float* topic_b   = (const float*)d_in[15];
    float* out = (float*)d_out;

    float *pH, *pXZ, *pU, *pDBC, *pDELTA;
    cudaGetSymbolAddress((void**)&pH,     g_H);
    cudaGetSymbolAddress((void**)&pXZ,    g_XZ);
    cudaGetSymbolAddress((void**)&pU,     g_U);
    cudaGetSymbolAddress((void**)&pDBC,   g_DBC);
    cudaGetSymbolAddress((void**)&pDELTA, g_DELTA);

    __nv_bfloat16 *pXNh, *pXNl, *pUh, *pUl, *pDBCh, *pDBCl, *pYh, *pYl;
    __nv_bfloat16 *pWih, *pWil, *pWxh, *pWxl, *pWdh, *pWdl, *pWoh, *pWol;
    cudaGetSymbolAddress((void**)&pXNh, g_XNh); cudaGetSymbolAddress((void**)&pXNl, g_XNl);
    cudaGetSymbolAddress((void**)&pUh,  g_Uh);  cudaGetSymbolAddress((void**)&pUl,  g_Ul);
    cudaGetSymbolAddress((void**)&pDBCh,g_DBCh);cudaGetSymbolAddress((void**)&pDBCl,g_DBCl);
    cudaGetSymbolAddress((void**)&pYh,  g_Yh);  cudaGetSymbolAddress((void**)&pYl,  g_Yl);
    cudaGetSymbolAddress((void**)&pWih, g_Wih); cudaGetSymbolAddress((void**)&pWil, g_Wil);
    cudaGetSymbolAddress((void**)&pWxh, g_Wxh); cudaGetSymbolAddress((void**)&pWxl, g_Wxl);
    cudaGetSymbolAddress((void**)&pWdh, g_Wdh); cudaGetSymbolAddress((void**)&pWdl, g_Wdl);
    cudaGetSymbolAddress((void**)&pWoh, g_Woh); cudaGetSymbolAddress((void**)&pWol, g_Wol);

    // one-time weight splits (cheap; runs each replay)
    {
        int n1 = NLAY*2*DI*DM;
        split_kernel<<<(n1+255)/256, 256>>>(in_proj_w, pWih, pWil, n1);
        int n2 = NLAY*DXP*DI;
        split_kernel<<<(n2+255)/256, 256>>>(x_proj_w, pWxh, pWxl, n2);
        int n3 = NLAY*DI*DR;
        split_kernel<<<(n3+255)/256, 256>>>(dt_proj_w, pWdh, pWdl, n3);
        int n4 = NLAY*DM*DI;
        split_kernel<<<(n4+255)/256, 256>>>(out_proj_w, pWoh, pWol, n4);
    }

    embed_kernel<<<(NROWS*DM + 255)/256, 256>>>(tokens, emb);

    for (int l = 0; l < NLAY; l++) {
        const __nv_bfloat16* ipwh = pWih + (size_t)l * 2*DI * DM;
        const __nv_bfloat16* ipwl = pWil + (size_t)l * 2*DI * DM;
        const __nv_bfloat16* xpwh = pWxh + (size_t)l * DXP * DI;
        const __nv_bfloat16* xpwl = pWxl + (size_t)l * DXP * DI;
        const __nv_bfloat16* dpwh = pWdh + (size_t)l * DI * DR;
        const __nv_bfloat16* dpwl = pWdl + (size_t)l * DI * DR;
        const __nv_bfloat16* opwh = pWoh + (size_t)l * DM * DI;
        const __nv_bfloat16* opwl = pWol + (size_t)l * DM * DI;
        const float* cw  = conv_w    + (size_t)l * DI * DCV;
        const float* cb  = conv_b    + (size_t)l * DI;
        const float* dpb = dt_proj_b + (size_t)l * DI;
        const float* Al  = A_log     + (size_t)l * DI * DS;
        const float* Dl  = Dp        + (size_t)l * DI;
        const float* nw  = norm_w    + (size_t)l * DM;

        // rmsnorm(h) -> XN hi/lo
        rmsnorm_split_kernel<<<NROWS, 256>>>(pH, nw, pXNh, pXNl);

        // XZ = XN @ in_proj^T  (4096 x 3072, K=768)
        {
            dim3 grid(2*DI/TN, NROWS/TM, 1);
            mmgemm<0><<<grid, 256>>>(pXNh, pXNl, ipwh, ipwl, pXZ, nullptr,
                                     2*DI, DM, DM, DM, DM);
        }

        // conv + silu -> U fp32 + hi/lo
        conv_silu_kernel<<<(NROWS*DI + 255)/256, 256>>>(cw, cb);

        // DBC = U @ x_proj^T  (4096 x 80, K=1536)  split-K=4 atomic
        zero_kernel<<<(NROWS*DXP + 255)/256, 256>>>(pDBC, NROWS*DXP);
        {
            dim3 grid(1, NROWS/TM, 4);
            mmgemm<3><<<grid, 256>>>(pUh, pUl, xpwh, xpwl, pDBC, nullptr,
                                     DXP, DI, DI, DI, DI/4);
        }

        // DBC -> hi/lo for dt GEMM
        split_kernel<<<(NROWS*DXP + 255)/256, 256>>>(pDBC, pDBCh, pDBCl, NROWS*DXP);

        // DELTA = softplus(DBC[:, :48] @ dt_proj^T + b)  (4096 x 1536, K=48)
        {
            dim3 grid(DI/TN, NROWS/TM, 1);
            mmgemm<2><<<grid, 256>>>(pDBCh, pDBCl, dpwh, dpwl, pDELTA, dpb,
                                     DI, DR, DXP, DR, 64);
        }

        // selective scan + gate -> Y hi/lo
        scan_kernel<<<BB*DI/16, 256>>>(Al, Dl);

        // H += Y @ out_proj^T  (4096 x 768, K=1536)  split-K=2 atomic into residual
        {
            dim3 grid(DM/TN, NROWS/TM, 2);
            mmgemm<3><<<grid, 256>>>(pYh, pYl, opwh, opwl, pH, nullptr,
                                     DM, DI, DI, DI, DI/2);
        }
    }

    rmsnorm_kernel<<<NROWS, 256>>>(pH, norm_f_w, out + 7);
    topic_kernel<<<1, 192>>>(out + 7, topic_w, topic_b, out);
    loss_kernel<<<1, 1>>>(out, labels);
}

// round 5
// speedup vs baseline: 2.8509x; 2.8509x over previous
#include <cuda_runtime.h>
#include <cuda_bf16.h>
#include <mma.h>
#include <math.h>

using namespace nvcuda;

// ---------------- problem constants ----------------
#define BB 2
#define LL 2048
#define NC 3
#define DMC 256
#define DM 768          // DMC*NC
#define DI 1536         // 2*DM
#define DS 16
#define DR 48
#define DCV 4
#define NLAY 4
#define DXP 80          // DR + 2*DS
#define NROWS (BB*LL)   // 4096
#define NCHK 32
#define CLEN 64         // LL / NCHK

// ---------------- scratch (device globals; no allocs) ----------------
__device__ float g_H[NROWS*DM];
__device__ float g_XZ[NROWS*2*DI];
__device__ float g_U[NROWS*DI];
__device__ float g_DBC[NROWS*DXP];
__device__ float g_DELTA[NROWS*DI];
__device__ float g_CP[BB*DI*NCHK*DS];   // chunk decay products
__device__ float g_CH[BB*DI*NCHK*DS];   // chunk end-states -> start-states

// bf16 hi/lo operand buffers
__device__ __nv_bfloat16 g_XNh[NROWS*DM],  g_XNl[NROWS*DM];
__device__ __nv_bfloat16 g_Uh[NROWS*DI],   g_Ul[NROWS*DI];
__device__ __nv_bfloat16 g_DBCh[NROWS*DXP],g_DBCl[NROWS*DXP];
__device__ __nv_bfloat16 g_Yh[NROWS*DI],   g_Yl[NROWS*DI];

// bf16 hi/lo weights (all layers)
__device__ __nv_bfloat16 g_Wih[NLAY*2*DI*DM], g_Wil[NLAY*2*DI*DM];
__device__ __nv_bfloat16 g_Wxh[NLAY*DXP*DI],  g_Wxl[NLAY*DXP*DI];
__device__ __nv_bfloat16 g_Wdh[NLAY*DI*DR],   g_Wdl[NLAY*DI*DR];
__device__ __nv_bfloat16 g_Woh[NLAY*DM*DI],   g_Wol[NLAY*DM*DI];

#define NW1 (NLAY*2*DI*DM)
#define NW2 (NLAY*DXP*DI)
#define NW3 (NLAY*DI*DR)
#define NW4 (NLAY*DM*DI)
#define NWTOT (NW1+NW2+NW3+NW4)

__device__ __forceinline__ void split_bf16(float x, __nv_bfloat16& h, __nv_bfloat16& l) {
    h = __float2bfloat16(x);
    l = __float2bfloat16(x - __bfloat162float(h));
}

// ---------------- cp.async helpers ----------------
__device__ __forceinline__ void cp16(void* smem, const void* gmem, bool pred) {
    unsigned s = (unsigned)__cvta_generic_to_shared(smem);
    int sz = pred ? 16 : 0;
    asm volatile("cp.async.cg.shared.global [%0], [%1], 16, %2;\n"
                 :: "r"(s), "l"(gmem), "r"(sz));
}
__device__ __forceinline__ void cp_commit() { asm volatile("cp.async.commit_group;\n"); }
template<int N> __device__ __forceinline__ void cp_wait() {
    asm volatile("cp.async.wait_group %0;\n" :: "n"(N));
}

// ---------------- fused weight split ----------------
__global__ void splitw_kernel(const float* __restrict__ w1, const float* __restrict__ w2,
                              const float* __restrict__ w3, const float* __restrict__ w4) {
    int i = blockIdx.x * blockDim.x + threadIdx.x;
    if (i >= NWTOT) return;
    float v; __nv_bfloat16 *ph, *pl; int o;
    if (i < NW1)                { o = i;             v = w1[o]; ph = g_Wih; pl = g_Wil; }
    else if (i < NW1+NW2)       { o = i-NW1;         v = w2[o]; ph = g_Wxh; pl = g_Wxl; }
    else if (i < NW1+NW2+NW3)   { o = i-NW1-NW2;     v = w3[o]; ph = g_Wdh; pl = g_Wdl; }
    else                        { o = i-NW1-NW2-NW3; v = w4[o]; ph = g_Woh; pl = g_Wol; }
    __nv_bfloat16 h, l;
    split_bf16(v, h, l);
    ph[o] = h; pl[o] = l;
}

__global__ void split_kernel(const float* __restrict__ w,
                             __nv_bfloat16* __restrict__ hi,
                             __nv_bfloat16* __restrict__ lo, int n) {
    int i = blockIdx.x * blockDim.x + threadIdx.x;
    if (i >= n) return;
    __nv_bfloat16 h, l;
    split_bf16(w[i], h, l);
    hi[i] = h; lo[i] = l;
}

// ---------------- embedding gather ----------------
__global__ void embed_kernel(const int* __restrict__ tokens,
                             const float* __restrict__ emb) {
    int i = blockIdx.x * blockDim.x + threadIdx.x;
    if (i >= NROWS*DM) return;
    int row = i / DM;
    int col = i % DM;
    int c = col / DMC, j = col % DMC;
    int tok = tokens[row*NC + c];
    g_H[i] = emb[tok*DMC + j];
}

// ---------------- rmsnorm variants ----------------
__global__ void rmsnorm_kernel(const float* __restrict__ in,
                               const float* __restrict__ w,
                               float* __restrict__ out) {
    int row = blockIdx.x;
    const float* x = in + (size_t)row*DM;
    float s = 0.f;
    for (int i = threadIdx.x; i < DM; i += 256) { float v = x[i]; s += v*v; }
    __shared__ float red[256];
    red[threadIdx.x] = s;
    __syncthreads();
    for (int o = 128; o; o >>= 1) {
        if (threadIdx.x < o) red[threadIdx.x] += red[threadIdx.x + o];
        __syncthreads();
    }
    float scale = rsqrtf(red[0] / (float)DM + 1e-5f);
    for (int i = threadIdx.x; i < DM; i += 256)
        out[(size_t)row*DM + i] = x[i] * scale * w[i];
}

__global__ void rmsnorm_split_kernel(const float* __restrict__ in,
                                     const float* __restrict__ w,
                                     __nv_bfloat16* __restrict__ oh,
                                     __nv_bfloat16* __restrict__ ol) {
    int row = blockIdx.x;
    const float* x = in + (size_t)row*DM;
    float s = 0.f;
    for (int i = threadIdx.x; i < DM; i += 256) { float v = x[i]; s += v*v; }
    __shared__ float red[256];
    red[threadIdx.x] = s;
    __syncthreads();
    for (int o = 128; o; o >>= 1) {
        if (threadIdx.x < o) red[threadIdx.x] += red[threadIdx.x + o];
        __syncthreads();
    }
    float scale = rsqrtf(red[0] / (float)DM + 1e-5f);
    for (int i = threadIdx.x; i < DM; i += 256) {
        float v = x[i] * scale * w[i];
        __nv_bfloat16 h, l;
        split_bf16(v, h, l);
        oh[(size_t)row*DM + i] = h;
        ol[(size_t)row*DM + i] = l;
    }
}

// ---------------- zero fill ----------------
__global__ void zero_kernel(float* __restrict__ p, int n) {
    int i = blockIdx.x * blockDim.x + threadIdx.x;
    if (i < n) p[i] = 0.f;
}

// ============================================================
// Tensor-core GEMM, bf16 hi/lo (3 MMAs), cp.async double-buffered.
// C[M,N] = A[M,K] * W[N,K]^T. Block 128x128, K-tile 32, 8 warps.
// EPI: 0 = store fp32, 2 = softplus(acc+bias[n]), 3 = atomicAdd
// ============================================================
#define TM 128
#define TN 128
#define TK 32
#define TLD 40
#define BUFE (TM*TLD)
#define GEMM_SMEM (8*BUFE*sizeof(__nv_bfloat16))  // 81920 B

template<int EPI>
__global__ __launch_bounds__(256)
void mmgemm(const __nv_bfloat16* __restrict__ Ah, const __nv_bfloat16* __restrict__ Al,
            const __nv_bfloat16* __restrict__ Wh, const __nv_bfloat16* __restrict__ Wl,
            float* __restrict__ C, const float* __restrict__ bias,
            int N, int Kmax, int lda, int ldw, int kchunk) {
    extern __shared__ __nv_bfloat16 smem[];
    __nv_bfloat16* sAh = smem;
    __nv_bfloat16* sAl = smem + 2*BUFE;
    __nv_bfloat16* sBh = smem + 4*BUFE;
    __nv_bfloat16* sBl = smem + 6*BUFE;

    int m0 = blockIdx.y * TM;
    int n0 = blockIdx.x * TN;
    int kb = blockIdx.z * kchunk;
    int ke = kb + kchunk;

    int tid  = threadIdx.x;
    int row  = tid >> 1;
    int koff = (tid & 1) * 16;
    int warp = tid >> 5;
    int lid  = tid & 31;
    int wm = warp & 3;
    int wn = warp >> 2;

    wmma::fragment<wmma::accumulator, 16, 16, 16, float> acc[2][4];
    #pragma unroll
    for (int i = 0; i < 2; i++)
        #pragma unroll
        for (int j = 0; j < 4; j++)
            wmma::fill_fragment(acc[i][j], 0.f);

    bool wrow_ok = (n0 + row) < N;
    const __nv_bfloat16* apH = Ah + (size_t)(m0 + row) * lda;
    const __nv_bfloat16* apL = Al + (size_t)(m0 + row) * lda;
    const __nv_bfloat16* wpH = Wh + (size_t)(wrow_ok ? (n0 + row) : 0) * ldw;
    const __nv_bfloat16* wpL = Wl + (size_t)(wrow_ok ? (n0 + row) : 0) * ldw;

    auto load_stage = [&](int buf, int kt) {
        #pragma unroll
        for (int h = 0; h < 2; h++) {
            int kc = kt + koff + h*8;
            bool kok = kc < Kmax;
            int so = buf*BUFE + row*TLD + koff + h*8;
            cp16(sAh + so, apH + kc, kok);
            cp16(sAl + so, apL + kc, kok);
            cp16(sBh + so, wpH + kc, kok && wrow_ok);
            cp16(sBl + so, wpL + kc, kok && wrow_ok);
        }
    };

    load_stage(0, kb);
    cp_commit();

    int buf = 0;
    for (int kt = kb; kt < ke; kt += TK) {
        bool hn = (kt + TK) < ke;
        if (hn) { load_stage(buf ^ 1, kt + TK); cp_commit(); }
        if (hn) cp_wait<1>(); else cp_wait<0>();
        __syncthreads();

        int bo = buf*BUFE;
        #pragma unroll
        for (int ks = 0; ks < TK; ks += 16) {
            wmma::fragment<wmma::matrix_a, 16, 16, 16, __nv_bfloat16, wmma::row_major> fah[2], fal[2];
            wmma::fragment<wmma::matrix_b, 16, 16, 16, __nv_bfloat16, wmma::col_major> fbh[4], fbl[4];
            #pragma unroll
            for (int i = 0; i < 2; i++) {
                wmma::load_matrix_sync(fah[i], sAh + bo + (wm*32 + 16*i)*TLD + ks, TLD);
                wmma::load_matrix_sync(fal[i], sAl + bo + (wm*32 + 16*i)*TLD + ks, TLD);
            }
            #pragma unroll
            for (int j = 0; j < 4; j++) {
                wmma::load_matrix_sync(fbh[j], sBh + bo + (wn*64 + 16*j)*TLD + ks, TLD);
                wmma::load_matrix_sync(fbl[j], sBl + bo + (wn*64 + 16*j)*TLD + ks, TLD);
            }
            #pragma unroll
            for (int i = 0; i < 2; i++)
                #pragma unroll
                for (int j = 0; j < 4; j++) {
                    wmma::mma_sync(acc[i][j], fah[i], fbh[j], acc[i][j]);
                    wmma::mma_sync(acc[i][j], fah[i], fbl[j], acc[i][j]);
                    wmma::mma_sync(acc[i][j], fal[i], fbh[j], acc[i][j]);
                }
        }
        __syncthreads();
        buf ^= 1;
    }

    if (EPI == 0) {
        #pragma unroll
        for (int i = 0; i < 2; i++)
            #pragma unroll
            for (int j = 0; j < 4; j++)
                wmma::store_matrix_sync(C + (size_t)(m0 + wm*32 + 16*i)*N + n0 + wn*64 + 16*j,
                                        acc[i][j], N, wmma::mem_row_major);
    } else {
        float* scratch = reinterpret_cast<float*>(smem) + warp * 320;
        #pragma unroll
        for (int i = 0; i < 2; i++)
            #pragma unroll
            for (int j = 0; j < 4; j++) {
                __syncwarp();
                wmma::store_matrix_sync(scratch, acc[i][j], 20, wmma::mem_row_major);
                __syncwarp();
                #pragma unroll
                for (int e = 0; e < 8; e++) {
                    int idx = lid*8 + e;
                    int r = idx >> 4, c = idx & 15;
                    int n = n0 + wn*64 + 16*j + c;
                    if (n < N) {
                        int m = m0 + wm*32 + 16*i + r;
                        size_t o = (size_t)m*N + n;
                        float v = scratch[r*20 + c];
                        if (EPI == 2) {
                            float t = v + bias[n];
                            C[o] = (t > 20.f) ? t : log1pf(expf(t));
                        } else {
                            atomicAdd(&C[o], v);
                        }
                    }
                }
            }
    }
}

// ---------------- depthwise causal conv + bias + silu -> U fp32 + hi/lo ----------------
__global__ void conv_silu_kernel(const float* __restrict__ cw,
                                 const float* __restrict__ cb) {
    int i = blockIdx.x * blockDim.x + threadIdx.x;
    if (i >= NROWS*DI) return;
    int d = i % DI;
    int row = i / DI;
    int t = row % LL, b = row / LL;
    float w0 = cw[d*DCV + 0], w1 = cw[d*DCV + 1], w2 = cw[d*DCV + 2], w3 = cw[d*DCV + 3];
    float acc = cb[d];
    const float* base = g_XZ + (size_t)(b*LL)*(2*DI) + d;
    if (t >= 3) acc += base[(size_t)(t-3)*(2*DI)] * w0;
    if (t >= 2) acc += base[(size_t)(t-2)*(2*DI)] * w1;
    if (t >= 1) acc += base[(size_t)(t-1)*(2*DI)] * w2;
    acc += base[(size_t)t*(2*DI)] * w3;
    float y = acc / (1.f + expf(-acc));
    g_U[i] = y;
    __nv_bfloat16 h, l;
    split_bf16(y, h, l);
    g_Uh[i] = h; g_Ul[i] = l;
}

// ============================================================
// Chunked selective scan (3 phases).
// Group = 16 lanes, one (channel, chunk). gi = c*(B*DI) + ch.
// ============================================================
__global__ void scanA_kernel(const float* __restrict__ A_log_l) {
    int tid = threadIdx.x;
    int s = tid & 15;
    int gi = blockIdx.x * 16 + (tid >> 4);
    int ch = gi % (BB*DI);
    int c  = gi / (BB*DI);
    int b = ch / DI, d = ch % DI;

    float A = -expf(A_log_l[d*DS + s]);
    const float* delta_p = g_DELTA + ((size_t)(b*LL) + c*CLEN)*DI + d;
    const float* u_p     = g_U     + ((size_t)(b*LL) + c*CLEN)*DI + d;
    const float* dbc_p   = g_DBC   + ((size_t)(b*LL) + c*CLEN)*DXP;

    float h = 0.f, P = 1.f;
    for (int t = 0; t < CLEN; t++) {
        float dt = delta_p[(size_t)t*DI];
        float ut = u_p[(size_t)t*DI];
        float Bs = dbc_p[(size_t)t*DXP + DR + s];
        float dA = __expf(dt * A);
        h = dA * h + (dt * ut) * Bs;
        P *= dA;
    }
    size_t idx = ((size_t)ch*NCHK + c)*DS + s;
    g_CH[idx] = h;
    g_CP[idx] = P;
}

__global__ void scanB_kernel() {
    int i = blockIdx.x * blockDim.x + threadIdx.x;   // i = ch*DS + s
    if (i >= BB*DI*DS) return;
    int ch = i >> 4, s = i & 15;
    size_t base = (size_t)ch*NCHK*DS + s;
    float h0 = 0.f;
    for (int c = 0; c < NCHK; c++) {
        float he = g_CH[base + (size_t)c*DS];
        float P  = g_CP[base + (size_t)c*DS];
        g_CH[base + (size_t)c*DS] = h0;   // start-state for chunk c
        h0 = P * h0 + he;
    }
}

__global__ void scanC_kernel(const float* __restrict__ A_log_l,
                             const float* __restrict__ D_l) {
    int tid = threadIdx.x;
    int s = tid & 15;
    int gi = blockIdx.x * 16 + (tid >> 4);
    int ch = gi % (BB*DI);
    int c  = gi / (BB*DI);
    int b = ch / DI, d = ch % DI;

    float A = -expf(A_log_l[d*DS + s]);
    float Dd = D_l[d];
    float h = g_CH[((size_t)ch*NCHK + c)*DS + s];

    const float* delta_p = g_DELTA + ((size_t)(b*LL) + c*CLEN)*DI + d;
    const float* u_p     = g_U     + ((size_t)(b*LL) + c*CLEN)*DI + d;
    const float* z_p     = g_XZ    + ((size_t)(b*LL) + c*CLEN)*(2*DI) + DI + d;
    const float* dbc_p   = g_DBC   + ((size_t)(b*LL) + c*CLEN)*DXP;
    size_t ybase         = ((size_t)(b*LL) + c*CLEN)*DI + d;

    for (int t = 0; t < CLEN; t++) {
        float dt = delta_p[(size_t)t*DI];
        float ut = u_p[(size_t)t*DI];
        float Bs = dbc_p[(size_t)t*DXP + DR + s];
        float Cs = dbc_p[(size_t)t*DXP + DR + DS + s];
        float dA = __expf(dt * A);
        h = dA * h + (dt * ut) * Bs;
        float yv = h * Cs;
        yv += __shfl_down_sync(0xffffffffu, yv, 8, 16);
        yv += __shfl_down_sync(0xffffffffu, yv, 4, 16);
        yv += __shfl_down_sync(0xffffffffu, yv, 2, 16);
        yv += __shfl_down_sync(0xffffffffu, yv, 1, 16);
        if (s == 0) {
            float z = z_p[(size_t)t*(2*DI)];
            float silu_z = z / (1.f + __expf(-z));
            float yo = (yv + ut * Dd) * silu_z;
            __nv_bfloat16 hh, ll;
            split_bf16(yo, hh, ll);
            g_Yh[ybase + (size_t)t*DI] = hh;
            g_Yl[ybase + (size_t)t*DI] = ll;
        }
    }
}

// ---------------- heads ----------------
__global__ void topic_kernel(const float* __restrict__ xfin,
                             const float* __restrict__ tw,
                             const float* __restrict__ tb,
                             float* __restrict__ out) {
    int w = threadIdx.x >> 5, lane = threadIdx.x & 31;
    if (w >= BB*3) return;
    int b = w / 3, c = w % 3;
    const float* p  = xfin + (size_t)(b*LL)*DM;
    const float* wt = tw + (size_t)c*DM;
    float s = 0.f;
    for (int i = lane; i < DM; i += 32) s += p[i] * wt[i];
    for (int o = 16; o; o >>= 1) s += __shfl_down_sync(0xffffffffu, s, o);
    if (lane == 0) out[b*3 + c] = s + tb[c];
}

__global__ void loss_kernel(float* __restrict__ out, const int* __restrict__ labels) {
    if (threadIdx.x != 0 || blockIdx.x != 0) return;
    float sum = 0.f, cnt = 0.f;
    for (int b = 0; b < BB; b++) {
        float t0 = out[b*3+0], t1 = out[b*3+1], t2 = out[b*3+2];
        float m = fmaxf(t0, fmaxf(t1, t2));
        float lse = m + logf(expf(t0-m) + expf(t1-m) + expf(t2-m));
        int lab = labels[b];
        float nll = lse - out[b*3 + lab];
        if (lab != 0) { sum += nll; cnt += 1.f; }
    }
    out[6] = sum / fmaxf(cnt, 1.f);
}

// ---------------- driver ----------------
extern "C" void kernel_launch(void* const* d_in, const int* in_sizes, int n_in,
                              void* d_out, int out_size) {
    const int*   tokens    = (const int*)  d_in[0];
    const int*   labels    = (const int*)  d_in[1];
    const float* emb       = (const float*)d_in[2];
    const float* in_proj_w = (const float*)d_in[3];
    const float* conv_w    = (const float*)d_in[4];
    const float* conv_b    = (const float*)d_in[5];
    const float* x_proj_w  = (const float*)d_in[6];
    const float* dt_proj_w = (const float*)d_in[7];
    const float* dt_proj_b = (const float*)d_in[8];
    const float* A_log     = (const float*)d_in[9];
    const float* Dp        = (const float*)d_in[10];
    const float* out_proj_w= (const float*)d_in[11];
    const float* norm_w    = (const float*)d_in[12];
    const float* norm_f_w  = (const float*)d_in[13];
    const float* topic_w   = (const float*)d_in[14];
    const float* topic_b   = (const float*)d_in[15];
    float* out = (float*)d_out;

    cudaFuncSetAttribute(mmgemm<0>, cudaFuncAttributeMaxDynamicSharedMemorySize, GEMM_SMEM);
    cudaFuncSetAttribute(mmgemm<2>, cudaFuncAttributeMaxDynamicSharedMemorySize, GEMM_SMEM);
    cudaFuncSetAttribute(mmgemm<3>, cudaFuncAttributeMaxDynamicSharedMemorySize, GEMM_SMEM);

    float *pH, *pXZ, *pDBC, *pDELTA;
    cudaGetSymbolAddress((void**)&pH,     g_H);
    cudaGetSymbolAddress((void**)&pXZ,    g_XZ);
    cudaGetSymbolAddress((void**)&pDBC,   g_DBC);
    cudaGetSymbolAddress((void**)&pDELTA, g_DELTA);

    __nv_bfloat16 *pXNh, *pXNl, *pUh, *pUl, *pDBCh, *pDBCl, *pYh, *pYl;
    __nv_bfloat16 *pWih, *pWil, *pWxh, *pWxl, *pWdh, *pWdl, *pWoh, *pWol;
    cudaGetSymbolAddress((void**)&pXNh, g_XNh); cudaGetSymbolAddress((void**)&pXNl, g_XNl);
    cudaGetSymbolAddress((void**)&pUh,  g_Uh);  cudaGetSymbolAddress((void**)&pUl,  g_Ul);
    cudaGetSymbolAddress((void**)&pDBCh,g_DBCh);cudaGetSymbolAddress((void**)&pDBCl,g_DBCl);
    cudaGetSymbolAddress((void**)&pYh,  g_Yh);  cudaGetSymbolAddress((void**)&pYl,  g_Yl);
    cudaGetSymbolAddress((void**)&pWih, g_Wih); cudaGetSymbolAddress((void**)&pWil, g_Wil);
    cudaGetSymbolAddress((void**)&pWxh, g_Wxh); cudaGetSymbolAddress((void**)&pWxl, g_Wxl);
    cudaGetSymbolAddress((void**)&pWdh, g_Wdh); cudaGetSymbolAddress((void**)&pWdl, g_Wdl);
    cudaGetSymbolAddress((void**)&pWoh, g_Woh); cudaGetSymbolAddress((void**)&pWol, g_Wol);

    // fused weight split (1 launch)
    splitw_kernel<<<(NWTOT + 255)/256, 256>>>(in_proj_w, x_proj_w, dt_proj_w, out_proj_w);

    embed_kernel<<<(NROWS*DM + 255)/256, 256>>>(tokens, emb);

    for (int l = 0; l < NLAY; l++) {
        const __nv_bfloat16* ipwh = pWih + (size_t)l * 2*DI * DM;
        const __nv_bfloat16* ipwl = pWil + (size_t)l * 2*DI * DM;
        const __nv_bfloat16* xpwh = pWxh + (size_t)l * DXP * DI;
        const __nv_bfloat16* xpwl = pWxl + (size_t)l * DXP * DI;
        const __nv_bfloat16* dpwh = pWdh + (size_t)l * DI * DR;
        const __nv_bfloat16* dpwl = pWdl + (size_t)l * DI * DR;
        const __nv_bfloat16* opwh = pWoh + (size_t)l * DM * DI;
        const __nv_bfloat16* opwl = pWol + (size_t)l * DM * DI;
        const float* cw  = conv_w    + (size_t)l * DI * DCV;
        const float* cb  = conv_b    + (size_t)l * DI;
        const float* dpb = dt_proj_b + (size_t)l * DI;
        const float* Al  = A_log     + (size_t)l * DI * DS;
        const float* Dl  = Dp        + (size_t)l * DI;
        const float* nw  = norm_w    + (size_t)l * DM;

        rmsnorm_split_kernel<<<NROWS, 256>>>(pH, nw, pXNh, pXNl);

        // XZ = XN @ in_proj^T  (4096 x 3072, K=768)
        {
            dim3 grid(2*DI/TN, NROWS/TM, 1);
            mmgemm<0><<<grid, 256, GEMM_SMEM>>>(pXNh, pXNl, ipwh, ipwl, pXZ, nullptr,
                                                2*DI, DM, DM, DM, DM);
        }

        conv_silu_kernel<<<(NROWS*DI + 255)/256, 256>>>(cw, cb);

        // DBC = U @ x_proj^T  (4096 x 80, K=1536)  split-K=4 atomic
        zero_kernel<<<(NROWS*DXP + 255)/256, 256>>>(pDBC, NROWS*DXP);
        {
            dim3 grid(1, NROWS/TM, 4);
            mmgemm<3><<<grid, 256, GEMM_SMEM>>>(pUh, pUl, xpwh, xpwl, pDBC, nullptr,
                                                DXP, DI, DI, DI, DI/4);
        }

        split_kernel<<<(NROWS*DXP + 255)/256, 256>>>(pDBC, pDBCh, pDBCl, NROWS*DXP);

        // DELTA = softplus(DBC[:, :48] @ dt_proj^T + b)  (4096 x 1536, K=48)
        {
            dim3 grid(DI/TN, NROWS/TM, 1);
            mmgemm<2><<<grid, 256, GEMM_SMEM>>>(pDBCh, pDBCl, dpwh, dpwl, pDELTA, dpb,
                                                DI, DR, DXP, DR, 64);
        }

        // chunked selective scan + gate -> Y hi/lo
        scanA_kernel<<<(BB*DI*NCHK)/16, 256>>>(Al);
        scanB_kernel<<<(BB*DI*DS + 255)/256, 256>>>();
        scanC_kernel<<<(BB*DI*NCHK)/16, 256>>>(Al, Dl);

        // H += Y @ out_proj^T  (4096 x 768, K=1536)  split-K=2 atomic into residual
        {
            dim3 grid(DM/TN, NROWS/TM, 2);
            mmgemm<3><<<grid, 256, GEMM_SMEM>>>(pYh, pYl, opwh, opwl, pH, nullptr,
                                                DM, DI, DI, DI, DI/2);
        }
    }

    rmsnorm_kernel<<<NROWS, 256>>>(pH, norm_f_w, out + 7);
    topic_kernel<<<1, 192>>>(out + 7, topic_w, topic_b, out);
    loss_kernel<<<1, 1>>>(out, labels);
}